// round 5
// baseline (speedup 1.0000x reference)
#include <cuda_runtime.h>
#include <cuda_bf16.h>
#include <cstdint>

#define H   2048
#define ISZ 4096
#define NE  8
#define T   2048

// ---------------- scratch: split bf16 planes (hi/lo) --------------------------
__device__ __nv_bfloat16 g_guph[8UL * 2048 * 8192];
__device__ __nv_bfloat16 g_gupl[8UL * 2048 * 8192];
__device__ __nv_bfloat16 g_dwnh[8UL * 4096 * 2048];
__device__ __nv_bfloat16 g_dwnl[8UL * 4096 * 2048];
__device__ __nv_bfloat16 g_sgh[2048UL * 4096];
__device__ __nv_bfloat16 g_sgl[2048UL * 4096];
__device__ __nv_bfloat16 g_suh[2048UL * 4096];
__device__ __nv_bfloat16 g_sul[2048UL * 4096];
__device__ __nv_bfloat16 g_sdh[4096UL * 2048];
__device__ __nv_bfloat16 g_sdl[4096UL * 2048];
__device__ __nv_bfloat16 g_xh[2048UL * 2048];
__device__ __nv_bfloat16 g_xl[2048UL * 2048];
__device__ __nv_bfloat16 g_acth[4096UL * 4096];   // rows 0..2047 shared, 2048..4095 routed
__device__ __nv_bfloat16 g_actl[4096UL * 4096];
__device__ float g_scale[T];
__device__ float g_scale_perm[T];
__device__ int   g_eid[T];
__device__ int   g_perm[T];
__device__ int   g_off[NE + 1];

#define MMA_BF16(d, a, b)                                                      \
    asm volatile("mma.sync.aligned.m16n8k16.row.col.f32.bf16.bf16.f32 "        \
                 "{%0,%1,%2,%3},{%4,%5,%6,%7},{%8,%9},{%0,%1,%2,%3};"          \
                 : "+f"(d[0]), "+f"(d[1]), "+f"(d[2]), "+f"(d[3])              \
                 : "r"(a[0]), "r"(a[1]), "r"(a[2]), "r"(a[3]),                 \
                   "r"(b[0]), "r"(b[1]))

__device__ __forceinline__ void ldsm_x4(uint32_t* r, uint32_t addr) {
    asm volatile("ldmatrix.sync.aligned.m8n8.x4.shared.b16 {%0,%1,%2,%3}, [%4];"
                 : "=r"(r[0]), "=r"(r[1]), "=r"(r[2]), "=r"(r[3]) : "r"(addr));
}
__device__ __forceinline__ void ldsm_x4t(uint32_t* r, uint32_t addr) {
    asm volatile("ldmatrix.sync.aligned.m8n8.x4.trans.shared.b16 {%0,%1,%2,%3}, [%4];"
                 : "=r"(r[0]), "=r"(r[1]), "=r"(r[2]), "=r"(r[3]) : "r"(addr));
}
__device__ __forceinline__ void cp16(uint32_t s, const void* g) {
    asm volatile("cp.async.cg.shared.global [%0], [%1], 16;\n" :: "r"(s), "l"(g));
}
__device__ __forceinline__ void cp_commit() { asm volatile("cp.async.commit_group;\n"); }
__device__ __forceinline__ void cp_wait1()  { asm volatile("cp.async.wait_group 1;\n"); }

// split pair (f0,f1) -> packed bf16x2 hi word + lo (residual) word
__device__ __forceinline__ void bpair(float f0, float f1, uint32_t& hw, uint32_t& lw) {
    __nv_bfloat162 h = __floats2bfloat162_rn(f0, f1);
    uint32_t hu = *reinterpret_cast<uint32_t*>(&h);
    float r0 = f0 - __uint_as_float(hu << 16);
    float r1 = f1 - __uint_as_float(hu & 0xffff0000u);
    __nv_bfloat162 l = __floats2bfloat162_rn(r0, r1);
    hw = hu;
    lw = *reinterpret_cast<uint32_t*>(&l);
}

// ---------------- split: fp32 -> hi/lo bf16 planes ----------------------------
__global__ void split_kernel(const float4* __restrict__ src, uint2* __restrict__ hi,
                             uint2* __restrict__ lo, long n4) {
    const long stride = (long)gridDim.x * blockDim.x;
    for (long i = (long)blockIdx.x * blockDim.x + threadIdx.x; i < n4; i += stride) {
        float4 v = src[i];
        uint32_t h0, h1, l0, l1;
        bpair(v.x, v.y, h0, l0);
        bpair(v.z, v.w, h1, l1);
        hi[i] = make_uint2(h0, h1);
        lo[i] = make_uint2(l0, l1);
    }
}

// ---------------- router ------------------------------------------------------
__global__ void router_kernel(const float* __restrict__ x, const float* __restrict__ rw) {
    const int t = blockIdx.x;
    const int tid = threadIdx.x;
    float acc[NE];
#pragma unroll
    for (int e = 0; e < NE; e++) acc[e] = 0.f;
    const float* xr = x + (size_t)t * H;
    for (int h = tid; h < H; h += 256) {
        float xv = xr[h];
#pragma unroll
        for (int e = 0; e < NE; e++) acc[e] += xv * rw[e * H + h];
    }
#pragma unroll
    for (int e = 0; e < NE; e++)
#pragma unroll
        for (int o = 16; o > 0; o >>= 1) acc[e] += __shfl_xor_sync(0xffffffffu, acc[e], o);
    __shared__ float red[NE][8];
    if ((tid & 31) == 0) {
#pragma unroll
        for (int e = 0; e < NE; e++) red[e][tid >> 5] = acc[e];
    }
    __syncthreads();
    if (tid == 0) {
        float best = -1e30f; int be = 0;
#pragma unroll
        for (int e = 0; e < NE; e++) {
            float v = 0.f;
#pragma unroll
            for (int w = 0; w < 8; w++) v += red[e][w];
            if (v > best) { best = v; be = e; }
        }
        g_scale[t] = 1.f / (1.f + expf(-best));
        g_eid[t] = be;
    }
}

// ---------------- bucket ------------------------------------------------------
__global__ void bucket_kernel() {
    __shared__ int cnt[NE], cur[NE];
    const int tid = threadIdx.x;
    if (tid < NE) cnt[tid] = 0;
    __syncthreads();
    for (int t = tid; t < T; t += 256) atomicAdd(&cnt[g_eid[t]], 1);
    __syncthreads();
    if (tid == 0) {
        int a = 0;
        for (int e = 0; e < NE; e++) { g_off[e] = a; cur[e] = a; a += cnt[e]; }
        g_off[NE] = a;
    }
    __syncthreads();
    for (int t = tid; t < T; t += 256) {
        int e = g_eid[t];
        int p = atomicAdd(&cur[e], 1);
        g_perm[p] = t;
        g_scale_perm[p] = g_scale[t];
    }
}

// SMEM layout (bytes), shared by both GEMMs:
//  A: 3 stages x 2 planes x 128 rows x 80B         = 61440
//  B: 3 stages x 2 planes x 32 rows x 272B         = 52224
#define A_PLANE 10240
#define A_STAGE 20480
#define B_BASE  61440
#define B_PLANE 8704
#define B_STAGE 17408
#define SMEM_SZ 113664
#define NS 3

// ---------------- GEMM1: x[M,2048] x (gate|up)[2048, 64+64] + SwiGLU ----------
__global__ __launch_bounds__(256) void gemm1_kernel() {
    extern __shared__ __align__(16) char smem[];
    const uint32_t sbase = (uint32_t)__cvta_generic_to_shared(smem);

    const int mTile = blockIdx.x, nTile = blockIdx.y, e = blockIdx.z;
    int M, offE, actBase;
    size_t ldb;
    const __nv_bfloat16 *bgate[2], *bup[2];
    if (e < NE) {
        offE = g_off[e]; M = g_off[e + 1] - offE;
        if (mTile * 128 >= M) return;
        const size_t wb = (size_t)e * H * (2 * ISZ) + (size_t)nTile * 64;
        bgate[0] = g_guph + wb; bgate[1] = g_gupl + wb;
        bup[0] = bgate[0] + ISZ; bup[1] = bgate[1] + ISZ;
        ldb = 2 * ISZ; actBase = T + offE;
    } else {
        offE = 0; M = T;
        bgate[0] = g_sgh + (size_t)nTile * 64; bgate[1] = g_sgl + (size_t)nTile * 64;
        bup[0]   = g_suh + (size_t)nTile * 64; bup[1]   = g_sul + (size_t)nTile * 64;
        ldb = ISZ; actBase = 0;
    }
    const int tid = threadIdx.x, lane = tid & 31, warp = tid >> 5;
    const int wm = warp & 3, wn = warp >> 2;

    // A loader: arow = tid>>1, half = tid&1 (two 16B chunks each of two planes)
    const int ahalf = tid & 1, arow = tid >> 1;
    const int lr = mTile * 128 + arow;
    int rowIdx = (e < NE) ? g_perm[offE + min(lr, M - 1)] : lr;
    const __nv_bfloat16* aptr[2] = { g_xh + (size_t)rowIdx * H + ahalf * 16,
                                     g_xl + (size_t)rowIdx * H + ahalf * 16 };
    const uint32_t aSm = arow * 80 + ahalf * 32;

    // B loader: krow = tid>>3, chunks bc0,bc0+1 (gate if bc0<8 else up)
    const int bkrow = tid >> 3, bc0 = (tid & 7) * 2;
    const bool bupf = bc0 >= 8;
    const __nv_bfloat16* bptr[2] = {
        (bupf ? bup[0] : bgate[0]) + (size_t)bkrow * ldb + (bc0 - (bupf ? 8 : 0)) * 8,
        (bupf ? bup[1] : bgate[1]) + (size_t)bkrow * ldb + (bc0 - (bupf ? 8 : 0)) * 8 };
    const uint32_t bSm = bkrow * 272 + bc0 * 16;

    // fragment offsets
    const int tq = lane >> 3, tr = lane & 7;
    uint32_t offA[2];
#pragma unroll
    for (int mi = 0; mi < 2; mi++) {
        int row = wm * 32 + mi * 16 + (tq & 1) * 8 + tr;
        offA[mi] = (uint32_t)(row * 80 + (tq >> 1) * 16);
    }
    const int kB = (tq & 1) * 8 + tr, ngB = tq >> 1;
    uint32_t offB[2][2];
#pragma unroll
    for (int hh = 0; hh < 2; hh++)
#pragma unroll
        for (int g = 0; g < 2; g++)
            offB[hh][g] = (uint32_t)(kB * 272 + (hh * 64 + wn * 32 + g * 16 + ngB * 8) * 2);

    float acc[2][2][4][4];
#pragma unroll
    for (int h = 0; h < 2; h++)
#pragma unroll
        for (int mi = 0; mi < 2; mi++)
#pragma unroll
            for (int ni = 0; ni < 4; ni++)
#pragma unroll
                for (int r = 0; r < 4; r++) acc[h][mi][ni][r] = 0.f;

    const int KT = H / 32;
    // prologue: stages 0,1
#pragma unroll
    for (int st = 0; st < NS - 1; st++) {
        const int k0 = st * 32;
        const uint32_t aS = sbase + st * A_STAGE + aSm;
        const uint32_t bS = sbase + B_BASE + st * B_STAGE + bSm;
#pragma unroll
        for (int p = 0; p < 2; p++) {
            cp16(aS + p * A_PLANE, aptr[p] + k0);
            cp16(aS + p * A_PLANE + 16, aptr[p] + k0 + 8);
            cp16(bS + p * B_PLANE, bptr[p] + (size_t)k0 * ldb);
            cp16(bS + p * B_PLANE + 16, bptr[p] + (size_t)k0 * ldb + 8);
        }
        cp_commit();
    }

    for (int kt = 0; kt < KT; ++kt) {
        cp_wait1();
        __syncthreads();
        if (kt + NS - 1 < KT) {
            const int st = (kt + NS - 1) % NS;
            const int k0 = (kt + NS - 1) * 32;
            const uint32_t aS = sbase + st * A_STAGE + aSm;
            const uint32_t bS = sbase + B_BASE + st * B_STAGE + bSm;
#pragma unroll
            for (int p = 0; p < 2; p++) {
                cp16(aS + p * A_PLANE, aptr[p] + k0);
                cp16(aS + p * A_PLANE + 16, aptr[p] + k0 + 8);
                cp16(bS + p * B_PLANE, bptr[p] + (size_t)k0 * ldb);
                cp16(bS + p * B_PLANE + 16, bptr[p] + (size_t)k0 * ldb + 8);
            }
        }
        cp_commit();

        const int s = kt % NS;
        const uint32_t aS = sbase + s * A_STAGE;
        const uint32_t bS = sbase + B_BASE + s * B_STAGE;
#pragma unroll
        for (int ks = 0; ks < 2; ++ks) {
            uint32_t ah[2][4], al[2][4];
            ldsm_x4(ah[0], aS + offA[0] + ks * 32);
            ldsm_x4(ah[1], aS + offA[1] + ks * 32);
            ldsm_x4(al[0], aS + A_PLANE + offA[0] + ks * 32);
            ldsm_x4(al[1], aS + A_PLANE + offA[1] + ks * 32);
#pragma unroll
            for (int hh = 0; hh < 2; ++hh) {
#pragma unroll
                for (int g = 0; g < 2; ++g) {
                    uint32_t bh4[4], bl4[4];
                    const uint32_t ob = bS + offB[hh][g] + ks * 16 * 272;
                    ldsm_x4t(bh4, ob);
                    ldsm_x4t(bl4, ob + B_PLANE);
#pragma unroll
                    for (int sub = 0; sub < 2; ++sub) {
                        const int ni = 2 * g + sub;
                        uint32_t bh[2] = { bh4[sub * 2], bh4[sub * 2 + 1] };
                        uint32_t bl[2] = { bl4[sub * 2], bl4[sub * 2 + 1] };
#pragma unroll
                        for (int mi = 0; mi < 2; ++mi) {
                            MMA_BF16(acc[hh][mi][ni], al[mi], bh);
                            MMA_BF16(acc[hh][mi][ni], ah[mi], bl);
                            MMA_BF16(acc[hh][mi][ni], ah[mi], bh);
                        }
                    }
                }
            }
        }
    }

    // epilogue: act = (s*up) * silu(s*gate), written as hi/lo bf16 planes
#pragma unroll
    for (int mi = 0; mi < 2; ++mi) {
        const int r0 = mTile * 128 + wm * 32 + mi * 16 + (lane >> 2);
        const int r1 = r0 + 8;
        const bool v0 = r0 < M, v1 = r1 < M;
        float s0 = 1.f, s1 = 1.f;
        if (e < NE) {
            s0 = v0 ? g_scale_perm[offE + r0] : 0.f;
            s1 = v1 ? g_scale_perm[offE + r1] : 0.f;
        }
#pragma unroll
        for (int ni = 0; ni < 4; ++ni) {
            const int col = nTile * 64 + wn * 32 + ni * 8 + (lane & 3) * 2;
            if (v0) {
                float gA = s0 * acc[0][mi][ni][0], gB = s0 * acc[0][mi][ni][1];
                float uA = s0 * acc[1][mi][ni][0], uB = s0 * acc[1][mi][ni][1];
                float a0 = uA * (gA / (1.f + expf(-gA)));
                float a1 = uB * (gB / (1.f + expf(-gB)));
                uint32_t hw, lw;
                bpair(a0, a1, hw, lw);
                const size_t idx = (size_t)(actBase + r0) * ISZ + col;
                *(uint32_t*)&g_acth[idx] = hw;
                *(uint32_t*)&g_actl[idx] = lw;
            }
            if (v1) {
                float gA = s1 * acc[0][mi][ni][2], gB = s1 * acc[0][mi][ni][3];
                float uA = s1 * acc[1][mi][ni][2], uB = s1 * acc[1][mi][ni][3];
                float a0 = uA * (gA / (1.f + expf(-gA)));
                float a1 = uB * (gB / (1.f + expf(-gB)));
                uint32_t hw, lw;
                bpair(a0, a1, hw, lw);
                const size_t idx = (size_t)(actBase + r1) * ISZ + col;
                *(uint32_t*)&g_acth[idx] = hw;
                *(uint32_t*)&g_actl[idx] = lw;
            }
        }
    }
}

// ---------------- GEMM2: act[M,4096] x down[4096,2048] ------------------------
__global__ __launch_bounds__(256) void gemm2_kernel(float* __restrict__ out, int routed) {
    extern __shared__ __align__(16) char smem[];
    const uint32_t sbase = (uint32_t)__cvta_generic_to_shared(smem);

    const int mTile = blockIdx.x, nTile = blockIdx.y;
    int M, offE, actBase;
    const __nv_bfloat16* bptrBase[2];
    if (routed) {
        const int e = blockIdx.z;
        offE = g_off[e]; M = g_off[e + 1] - offE;
        if (mTile * 128 >= M) return;
        actBase = T + offE;
        const size_t wb = (size_t)e * ISZ * H + (size_t)nTile * 128;
        bptrBase[0] = g_dwnh + wb; bptrBase[1] = g_dwnl + wb;
    } else {
        offE = 0; M = T; actBase = 0;
        bptrBase[0] = g_sdh + (size_t)nTile * 128;
        bptrBase[1] = g_sdl + (size_t)nTile * 128;
    }
    const int tid = threadIdx.x, lane = tid & 31, warp = tid >> 5;
    const int wm = warp & 3, wn = warp >> 2;

    const int ahalf = tid & 1, arow = tid >> 1;
    const int lr = mTile * 128 + arow;
    const size_t arIdx = (size_t)(actBase + min(lr, M - 1)) * ISZ + ahalf * 16;
    const __nv_bfloat16* aptr[2] = { g_acth + arIdx, g_actl + arIdx };
    const uint32_t aSm = arow * 80 + ahalf * 32;

    const int bkrow = tid >> 3, bc0 = (tid & 7) * 2;
    const __nv_bfloat16* bptr[2] = { bptrBase[0] + (size_t)bkrow * H + bc0 * 8,
                                     bptrBase[1] + (size_t)bkrow * H + bc0 * 8 };
    const uint32_t bSm = bkrow * 272 + bc0 * 16;

    const int tq = lane >> 3, tr = lane & 7;
    uint32_t offA[2];
#pragma unroll
    for (int mi = 0; mi < 2; mi++) {
        int row = wm * 32 + mi * 16 + (tq & 1) * 8 + tr;
        offA[mi] = (uint32_t)(row * 80 + (tq >> 1) * 16);
    }
    const int kB = (tq & 1) * 8 + tr, ngB = tq >> 1;
    uint32_t offB[4];
#pragma unroll
    for (int g = 0; g < 4; g++)
        offB[g] = (uint32_t)(kB * 272 + (wn * 64 + g * 16 + ngB * 8) * 2);

    float acc[2][8][4];
#pragma unroll
    for (int mi = 0; mi < 2; mi++)
#pragma unroll
        for (int ni = 0; ni < 8; ni++)
#pragma unroll
            for (int r = 0; r < 4; r++) acc[mi][ni][r] = 0.f;

    const int KT = ISZ / 32;
#pragma unroll
    for (int st = 0; st < NS - 1; st++) {
        const int k0 = st * 32;
        const uint32_t aS = sbase + st * A_STAGE + aSm;
        const uint32_t bS = sbase + B_BASE + st * B_STAGE + bSm;
#pragma unroll
        for (int p = 0; p < 2; p++) {
            cp16(aS + p * A_PLANE, aptr[p] + k0);
            cp16(aS + p * A_PLANE + 16, aptr[p] + k0 + 8);
            cp16(bS + p * B_PLANE, bptr[p] + (size_t)k0 * H);
            cp16(bS + p * B_PLANE + 16, bptr[p] + (size_t)k0 * H + 8);
        }
        cp_commit();
    }

    for (int kt = 0; kt < KT; ++kt) {
        cp_wait1();
        __syncthreads();
        if (kt + NS - 1 < KT) {
            const int st = (kt + NS - 1) % NS;
            const int k0 = (kt + NS - 1) * 32;
            const uint32_t aS = sbase + st * A_STAGE + aSm;
            const uint32_t bS = sbase + B_BASE + st * B_STAGE + bSm;
#pragma unroll
            for (int p = 0; p < 2; p++) {
                cp16(aS + p * A_PLANE, aptr[p] + k0);
                cp16(aS + p * A_PLANE + 16, aptr[p] + k0 + 8);
                cp16(bS + p * B_PLANE, bptr[p] + (size_t)k0 * H);
                cp16(bS + p * B_PLANE + 16, bptr[p] + (size_t)k0 * H + 8);
            }
        }
        cp_commit();

        const int s = kt % NS;
        const uint32_t aS = sbase + s * A_STAGE;
        const uint32_t bS = sbase + B_BASE + s * B_STAGE;
#pragma unroll
        for (int ks = 0; ks < 2; ++ks) {
            uint32_t ah[2][4], al[2][4];
            ldsm_x4(ah[0], aS + offA[0] + ks * 32);
            ldsm_x4(ah[1], aS + offA[1] + ks * 32);
            ldsm_x4(al[0], aS + A_PLANE + offA[0] + ks * 32);
            ldsm_x4(al[1], aS + A_PLANE + offA[1] + ks * 32);
#pragma unroll
            for (int g = 0; g < 4; ++g) {
                uint32_t bh4[4], bl4[4];
                const uint32_t ob = bS + offB[g] + ks * 16 * 272;
                ldsm_x4t(bh4, ob);
                ldsm_x4t(bl4, ob + B_PLANE);
#pragma unroll
                for (int sub = 0; sub < 2; ++sub) {
                    const int ni = 2 * g + sub;
                    uint32_t bh[2] = { bh4[sub * 2], bh4[sub * 2 + 1] };
                    uint32_t bl[2] = { bl4[sub * 2], bl4[sub * 2 + 1] };
#pragma unroll
                    for (int mi = 0; mi < 2; ++mi) {
                        MMA_BF16(acc[mi][ni], al[mi], bh);
                        MMA_BF16(acc[mi][ni], ah[mi], bl);
                        MMA_BF16(acc[mi][ni], ah[mi], bh);
                    }
                }
            }
        }
    }

#pragma unroll
    for (int mi = 0; mi < 2; ++mi) {
        const int r0 = mTile * 128 + wm * 32 + mi * 16 + (lane >> 2);
        const int r1 = r0 + 8;
        const bool v0 = r0 < M, v1 = r1 < M;
        int t0 = 0, t1 = 0;
        if (routed) {
            if (v0) t0 = g_perm[offE + r0];
            if (v1) t1 = g_perm[offE + r1];
        } else { t0 = r0; t1 = r1; }
#pragma unroll
        for (int ni = 0; ni < 8; ++ni) {
            const int col = nTile * 128 + wn * 64 + ni * 8 + (lane & 3) * 2;
            if (v0) {
                float2* p = (float2*)&out[(size_t)t0 * H + col];
                if (routed) {
                    float2 v = *p;
                    v.x += acc[mi][ni][0]; v.y += acc[mi][ni][1];
                    *p = v;
                } else {
                    *p = make_float2(acc[mi][ni][0], acc[mi][ni][1]);
                }
            }
            if (v1) {
                float2* p = (float2*)&out[(size_t)t1 * H + col];
                if (routed) {
                    float2 v = *p;
                    v.x += acc[mi][ni][2]; v.y += acc[mi][ni][3];
                    *p = v;
                } else {
                    *p = make_float2(acc[mi][ni][2], acc[mi][ni][3]);
                }
            }
        }
    }
}

// ---------------- launch ------------------------------------------------------
extern "C" void kernel_launch(void* const* d_in, const int* in_sizes, int n_in,
                              void* d_out, int out_size) {
    const float* x   = (const float*)d_in[0];
    const float* rw  = (const float*)d_in[1];
    const float* gup = (const float*)d_in[2];
    const float* dwn = (const float*)d_in[3];
    const float* sg  = (const float*)d_in[4];
    const float* su  = (const float*)d_in[5];
    const float* sd  = (const float*)d_in[6];
    float* out = (float*)d_out;

    cudaFuncSetAttribute(gemm1_kernel, cudaFuncAttributeMaxDynamicSharedMemorySize, SMEM_SZ);
    cudaFuncSetAttribute(gemm2_kernel, cudaFuncAttributeMaxDynamicSharedMemorySize, SMEM_SZ);

    __nv_bfloat16 *guph, *gupl, *dwnh, *dwnl, *sgh, *sgl, *suh, *sul, *sdh, *sdl, *xh, *xl;
    cudaGetSymbolAddress((void**)&guph, g_guph); cudaGetSymbolAddress((void**)&gupl, g_gupl);
    cudaGetSymbolAddress((void**)&dwnh, g_dwnh); cudaGetSymbolAddress((void**)&dwnl, g_dwnl);
    cudaGetSymbolAddress((void**)&sgh,  g_sgh);  cudaGetSymbolAddress((void**)&sgl,  g_sgl);
    cudaGetSymbolAddress((void**)&suh,  g_suh);  cudaGetSymbolAddress((void**)&sul,  g_sul);
    cudaGetSymbolAddress((void**)&sdh,  g_sdh);  cudaGetSymbolAddress((void**)&sdl,  g_sdl);
    cudaGetSymbolAddress((void**)&xh,   g_xh);   cudaGetSymbolAddress((void**)&xl,   g_xl);

    router_kernel<<<T, 256>>>(x, rw);
    bucket_kernel<<<1, 256>>>();

    split_kernel<<<8192, 256>>>((const float4*)gup, (uint2*)guph, (uint2*)gupl, 8L * 2048 * 8192 / 4);
    split_kernel<<<8192, 256>>>((const float4*)dwn, (uint2*)dwnh, (uint2*)dwnl, 8L * 4096 * 2048 / 4);
    split_kernel<<<2048, 256>>>((const float4*)sg,  (uint2*)sgh,  (uint2*)sgl,  2048L * 4096 / 4);
    split_kernel<<<2048, 256>>>((const float4*)su,  (uint2*)suh,  (uint2*)sul,  2048L * 4096 / 4);
    split_kernel<<<2048, 256>>>((const float4*)sd,  (uint2*)sdh,  (uint2*)sdl,  4096L * 2048 / 4);
    split_kernel<<<1024, 256>>>((const float4*)x,   (uint2*)xh,   (uint2*)xl,   2048L * 2048 / 4);

    gemm1_kernel<<<dim3(16, ISZ / 64, NE + 1), 256, SMEM_SZ>>>();
    gemm2_kernel<<<dim3(16, H / 128, 1), 256, SMEM_SZ>>>(out, 0);   // shared: writes out
    gemm2_kernel<<<dim3(16, H / 128, NE), 256, SMEM_SZ>>>(out, 1);  // routed: adds
}